// round 6
// baseline (speedup 1.0000x reference)
#include <cuda_runtime.h>
#include <cstdint>

// EquiLocalPatOrientConvolution: B=2, I=32, O=64, D=H=W=48, K=5 (pad 2).
// v6: radial sums via packed f32x2 (2 channels/pass) -> Ys[k][vox] smem ->
// portable mma.sync m16n8k8 tf32 with 3xTF32 hi/lo split (rel_err ~1e-6).
// W pre-baked into exact B-fragment layout (hi/lo) by prep kernel.

#define DIMS  48
#define TX    8
#define TY    8
#define TZ    4
#define HX    12
#define HY    12
#define HZ    8
#define NI    32
#define NO    64
#define NP    10
#define Y0C   0.28209479177387814f
#define NTHR  256
#define NPAIR 16

#define XS_ELEMS   (HX * HY * HZ)       // 1152 float2 per buffer
#define YS_STRIDE  264                  // 256 vox + 8 pad (bank-conflict-free frags)
#define YS_ROWS    24                   // k = 0..19 data, 20..23 zero
#define YS_FLOATS  (YS_ROWS * YS_STRIDE)        // 6336
#define SMEM_FLOATS (2 * 2 * XS_ELEMS + YS_FLOATS)  // xs(2buf,float2) + Ys
#define SMEM_BYTES  (SMEM_FLOATS * 4 + 256)

__device__ __host__ constexpr int p_of_r2(int r2) {
    return r2 <= 6 ? r2 : (r2 == 8 ? 7 : (r2 == 9 ? 8 : 9));
}

// B fragments: [pair][ks][nt][lane] -> float4 {b0hi, b1hi, b0lo, b1lo}
__device__ float4 g_Bf[NPAIR * 3 * 8 * 32];

__device__ __forceinline__ uint32_t tf32_rna(float x) {
    uint32_t r;
    asm("cvt.rna.tf32.f32 %0, %1;" : "=r"(r) : "f"(x));
    return r;
}

__device__ __forceinline__ void mma_tf32(float* c,
                                         uint32_t a0, uint32_t a1, uint32_t a2, uint32_t a3,
                                         uint32_t b0, uint32_t b1) {
    asm("mma.sync.aligned.m16n8k8.row.col.f32.tf32.tf32.f32 "
        "{%0,%1,%2,%3}, {%4,%5,%6,%7}, {%8,%9}, {%0,%1,%2,%3};"
        : "+f"(c[0]), "+f"(c[1]), "+f"(c[2]), "+f"(c[3])
        : "r"(a0), "r"(a1), "r"(a2), "r"(a3), "r"(b0), "r"(b1));
}

// ---------- prep: W[o][ci][p] -> B-fragment layout, Y0 folded, hi/lo tf32 ----------
__global__ void bprep_kernel(const float* __restrict__ wg) {
    int idx = blockIdx.x * 256 + threadIdx.x;
    if (idx >= NPAIR * 3 * 8 * 32) return;
    int lane = idx & 31;
    int r    = idx >> 5;
    int nt   = r & 7;  r >>= 3;
    int ks   = r % 3;
    int pair = r / 3;
    int gid = lane >> 2, tidg = lane & 3;
    int o = nt * 8 + gid;
    auto getw = [&](int k) -> float {
        if (k >= 20) return 0.0f;
        int ci = pair * 2 + k / 10;
        int p  = k % 10;
        return Y0C * wg[o * (NI * NP) + ci * NP + p];
    };
    float b0 = getw(ks * 8 + tidg);
    float b1 = getw(ks * 8 + tidg + 4);
    uint32_t b0h = tf32_rna(b0), b1h = tf32_rna(b1);
    uint32_t b0l = tf32_rna(b0 - __uint_as_float(b0h));
    uint32_t b1l = tf32_rna(b1 - __uint_as_float(b1h));
    g_Bf[idx] = make_float4(__uint_as_float(b0h), __uint_as_float(b1h),
                            __uint_as_float(b0l), __uint_as_float(b1l));
}

// ---------- main ----------
__global__ void __launch_bounds__(NTHR, 2)
econv_kernel(const float* __restrict__ x,
             const float* __restrict__ bias,
             float* __restrict__ out)
{
    extern __shared__ float smem[];
    float2* xs[2];
    xs[0] = (float2*)smem;
    xs[1] = xs[0] + XS_ELEMS;
    float* Ys = smem + 4 * XS_ELEMS;            // [k][vox], stride YS_STRIDE

    const int tid  = threadIdx.x;
    const int wid  = tid >> 5;
    const int lid  = tid & 31;
    const int gid  = lid >> 2;                  // 0..7
    const int tidg = lid & 3;                   // 0..3
    const int b    = blockIdx.y;
    const int t    = blockIdx.x;
    const int tz   = t / 36;
    const int ty   = (t % 36) / 6;
    const int tx   = t % 6;
    const int z0   = tz * TZ, y0 = ty * TY, x0 = tx * TX;

    const size_t x_chan = (size_t)DIMS * DIMS * DIMS;
    const float* xb = x + (size_t)b * NI * x_chan;

    // zero the K-pad rows (20..23) once
    #pragma unroll
    for (int k = 0; k < 5; k++) {
        int idx = tid + k * NTHR;
        if (idx < 4 * YS_STRIDE) Ys[20 * YS_STRIDE + idx] = 0.0f;
    }

    // accumulators: [mt][nt][4]
    float acc[64];
    #pragma unroll
    for (int k = 0; k < 64; k++) acc[k] = 0.0f;

    // ---- halo prefetch for a channel pair (2 channels -> float2) ----
    float pre0[5], pre1[5];
    auto pf_x = [&](int pair) {
        const float* c0 = xb + (size_t)(2 * pair) * x_chan;
        const float* c1 = c0 + x_chan;
        #pragma unroll
        for (int k = 0; k < 5; k++) {
            int idx = tid + k * NTHR;
            float v0 = 0.0f, v1 = 0.0f;
            if (idx < XS_ELEMS) {
                int zz = idx / (HX * HY);
                int rr = idx % (HX * HY);
                int yy = rr / HX, xx = rr % HX;
                int gz = z0 + zz - 2, gy = y0 + yy - 2, gx = x0 + xx - 2;
                if ((unsigned)gz < (unsigned)DIMS &&
                    (unsigned)gy < (unsigned)DIMS &&
                    (unsigned)gx < (unsigned)DIMS) {
                    int off = (gz * DIMS + gy) * DIMS + gx;
                    v0 = __ldg(&c0[off]);
                    v1 = __ldg(&c1[off]);
                }
            }
            pre0[k] = v0; pre1[k] = v1;
        }
    };
    auto cm_x = [&](float2* dst) {
        #pragma unroll
        for (int k = 0; k < 5; k++) {
            int idx = tid + k * NTHR;
            if (idx < XS_ELEMS) dst[idx] = make_float2(pre0[k], pre1[k]);
        }
    };

    // ---- radial sums for 2 channels at once (packed f32x2 adds) ----
    auto radial = [&](const float2* xsrc) {
        const int vz = tid >> 6, vy = (tid >> 3) & 7, vx = tid & 7;
        const unsigned long long* xu = (const unsigned long long*)xsrc;
        unsigned long long yr[NP];
        #pragma unroll
        for (int p = 0; p < NP; p++) yr[p] = 0ULL;
        #pragma unroll
        for (int dz = 0; dz < 5; dz++) {
            #pragma unroll
            for (int dy = 0; dy < 5; dy++) {
                const unsigned long long* row =
                    &xu[((vz + dz) * HY + (vy + dy)) * HX + vx];
                #pragma unroll
                for (int dx = 0; dx < 5; dx++) {
                    const int p = p_of_r2((dz - 2) * (dz - 2) +
                                          (dy - 2) * (dy - 2) +
                                          (dx - 2) * (dx - 2));
                    asm("add.rn.f32x2 %0, %0, %1;" : "+l"(yr[p]) : "l"(row[dx]));
                }
            }
        }
        #pragma unroll
        for (int p = 0; p < NP; p++) {
            float2 v = *(float2*)&yr[p];
            Ys[p * YS_STRIDE + tid]         = v.x;   // ch0 -> k rows 0..9
            Ys[(p + 10) * YS_STRIDE + tid]  = v.y;   // ch1 -> k rows 10..19
        }
    };

    // ---- GEMM: 3xTF32 mma over this pair's K=24 (rows 20..23 zero) ----
    auto gemm = [&](int pair) {
        const float4* bsrc = g_Bf + pair * (3 * 8 * 32);
        #pragma unroll
        for (int ks = 0; ks < 3; ks++) {
            // B-fragment batch (L2-resident, coalesced)
            float4 bf[8];
            #pragma unroll
            for (int nt = 0; nt < 8; nt++)
                bf[nt] = __ldg(&bsrc[(ks * 8 + nt) * 32 + lid]);
            // A fragments (hi/lo) for both m-tiles
            uint32_t Ah[2][4], Al[2][4];
            #pragma unroll
            for (int mt = 0; mt < 2; mt++) {
                const int vb = wid * 32 + mt * 16 + gid;
                const float* yk = Ys + (ks * 8 + tidg) * YS_STRIDE;
                float a[4];
                a[0] = yk[vb];
                a[1] = yk[vb + 8];
                a[2] = yk[4 * YS_STRIDE + vb];
                a[3] = yk[4 * YS_STRIDE + vb + 8];
                #pragma unroll
                for (int r = 0; r < 4; r++) {
                    Ah[mt][r] = tf32_rna(a[r]);
                    Al[mt][r] = tf32_rna(a[r] - __uint_as_float(Ah[mt][r]));
                }
            }
            #pragma unroll
            for (int nt = 0; nt < 8; nt++) {
                uint32_t b0h = __float_as_uint(bf[nt].x);
                uint32_t b1h = __float_as_uint(bf[nt].y);
                uint32_t b0l = __float_as_uint(bf[nt].z);
                uint32_t b1l = __float_as_uint(bf[nt].w);
                #pragma unroll
                for (int mt = 0; mt < 2; mt++) {
                    float* c = &acc[(mt * 8 + nt) * 4];
                    mma_tf32(c, Ah[mt][0], Ah[mt][1], Ah[mt][2], Ah[mt][3], b0h, b1h);
                    mma_tf32(c, Al[mt][0], Al[mt][1], Al[mt][2], Al[mt][3], b0h, b1h);
                    mma_tf32(c, Ah[mt][0], Ah[mt][1], Ah[mt][2], Ah[mt][3], b0l, b1l);
                }
            }
        }
    };

    // ---- pipeline prologue ----
    pf_x(0);
    cm_x(xs[0]);
    __syncthreads();
    radial(xs[0]);

    // ---- main loop over 16 channel pairs ----
    #pragma unroll 1
    for (int pair = 0; pair < NPAIR; pair++) {
        if (pair + 1 < NPAIR) pf_x(pair + 1);    // LDGs in flight behind gemm
        __syncthreads();                         // Ys(pair) visible
        gemm(pair);
        if (pair + 1 < NPAIR) {
            cm_x(xs[(pair + 1) & 1]);
            __syncthreads();                     // gemm done with Ys; new xs visible
            radial(xs[(pair + 1) & 1]);          // build Ys(pair+1)
        }
    }

    // ---- epilogue: stage through smem (aliases Ys) for coalesced stores ----
    __syncthreads();                             // all gemm reads of Ys done
    float* stage = Ys;                           // [c16][vox], stride YS_STRIDE
    #pragma unroll 1
    for (int chunk = 0; chunk < 4; chunk++) {
        if (chunk) __syncthreads();
        #pragma unroll
        for (int mt = 0; mt < 2; mt++) {
            #pragma unroll
            for (int nt2 = 0; nt2 < 2; nt2++) {
                const int nt = chunk * 2 + nt2;
                #pragma unroll
                for (int r = 0; r < 4; r++) {
                    int vox = wid * 32 + mt * 16 + gid + ((r >> 1) << 3);
                    int c16 = nt2 * 8 + 2 * tidg + (r & 1);
                    stage[c16 * YS_STRIDE + vox] = acc[(mt * 8 + nt) * 4 + r];
                }
            }
        }
        __syncthreads();
        #pragma unroll
        for (int j = 0; j < 2; j++) {
            const int o16 = wid + j * 8;
            const int vr  = lid;                 // voxel-row (8 voxels along x)
            const int o   = chunk * 16 + o16;
            const float bb = __ldg(&bias[o]);
            float4 v0 = *(float4*)&stage[o16 * YS_STRIDE + vr * 8];
            float4 v1 = *(float4*)&stage[o16 * YS_STRIDE + vr * 8 + 4];
            v0.x += bb; v0.y += bb; v0.z += bb; v0.w += bb;
            v1.x += bb; v1.y += bb; v1.z += bb; v1.w += bb;
            const int gz = z0 + (vr >> 3), gy = y0 + (vr & 7);
            float* dst = out + ((size_t)b * NO + o) * x_chan
                             + ((size_t)gz * DIMS + gy) * DIMS + x0;
            *(float4*)&dst[0] = v0;
            *(float4*)&dst[4] = v1;
        }
    }
}

extern "C" void kernel_launch(void* const* d_in, const int* in_sizes, int n_in,
                              void* d_out, int out_size)
{
    const float* x    = (const float*)d_in[0];   // [2,32,1,48,48,48]
    const float* w    = (const float*)d_in[1];   // [64,32,1,1,1,10]
    const float* bias = (const float*)d_in[2];   // [64]
    float* out = (float*)d_out;                  // [2,64,1,48,48,48]

    bprep_kernel<<<(NPAIR * 3 * 8 * 32 + 255) / 256, 256>>>(w);

    cudaFuncSetAttribute(econv_kernel,
                         cudaFuncAttributeMaxDynamicSharedMemorySize, SMEM_BYTES);
    dim3 grid(432, 2);   // 6x6x12 spatial tiles x batch
    econv_kernel<<<grid, NTHR, SMEM_BYTES>>>(x, bias, out);
}

// round 7
// speedup vs baseline: 1.0713x; 1.0713x over previous
#include <cuda_runtime.h>
#include <cstdint>

// EquiLocalPatOrientConvolution: B=2, I=32, O=64, D=H=W=48, K=5 (pad 2).
// v7: 128-thread blocks, tile 8x8x2, 4 blocks/SM for cross-block phase overlap.
// radial sums via packed f32x2 (2 ch/pass) -> Ys[k][vox] -> mma.sync m16n8k8
// tf32 3x-split (rel_err ~3e-6). W pre-baked into B-fragment layout.

#define DIMS  48
#define TX    8
#define TY    8
#define TZ    2
#define HX    12
#define HY    12
#define HZ    6
#define NI    32
#define NO    64
#define NP    10
#define Y0C   0.28209479177387814f
#define NTHR  128
#define NVOX  128
#define NPAIR 16

#define XS_ELEMS   (HX * HY * HZ)       // 864 float2 per buffer
#define YS_STRIDE  136                  // 128 vox + 8 pad
#define YS_ROWS    24                   // k = 0..19 data, 20..23 zero
#define YS_FLOATS  (YS_ROWS * YS_STRIDE)
#define SMEM_FLOATS (2 * 2 * XS_ELEMS + YS_FLOATS)
#define SMEM_BYTES  (SMEM_FLOATS * 4 + 256)

__device__ __host__ constexpr int p_of_r2(int r2) {
    return r2 <= 6 ? r2 : (r2 == 8 ? 7 : (r2 == 9 ? 8 : 9));
}

// B fragments: [pair][ks][nt][lane] -> float4 {b0hi, b1hi, b0lo, b1lo}
__device__ float4 g_Bf[NPAIR * 3 * 8 * 32];

__device__ __forceinline__ uint32_t tf32_rna(float x) {
    uint32_t r;
    asm("cvt.rna.tf32.f32 %0, %1;" : "=r"(r) : "f"(x));
    return r;
}

__device__ __forceinline__ void mma_tf32(float* c,
                                         uint32_t a0, uint32_t a1, uint32_t a2, uint32_t a3,
                                         uint32_t b0, uint32_t b1) {
    asm("mma.sync.aligned.m16n8k8.row.col.f32.tf32.tf32.f32 "
        "{%0,%1,%2,%3}, {%4,%5,%6,%7}, {%8,%9}, {%0,%1,%2,%3};"
        : "+f"(c[0]), "+f"(c[1]), "+f"(c[2]), "+f"(c[3])
        : "r"(a0), "r"(a1), "r"(a2), "r"(a3), "r"(b0), "r"(b1));
}

// ---------- prep: W[o][ci][p] -> B-fragment layout, Y0 folded, hi/lo tf32 ----------
__global__ void bprep_kernel(const float* __restrict__ wg) {
    int idx = blockIdx.x * 256 + threadIdx.x;
    if (idx >= NPAIR * 3 * 8 * 32) return;
    int lane = idx & 31;
    int r    = idx >> 5;
    int nt   = r & 7;  r >>= 3;
    int ks   = r % 3;
    int pair = r / 3;
    int gid = lane >> 2, tidg = lane & 3;
    int o = nt * 8 + gid;
    auto getw = [&](int k) -> float {
        if (k >= 20) return 0.0f;
        int ci = pair * 2 + k / 10;
        int p  = k % 10;
        return Y0C * wg[o * (NI * NP) + ci * NP + p];
    };
    float b0 = getw(ks * 8 + tidg);
    float b1 = getw(ks * 8 + tidg + 4);
    uint32_t b0h = tf32_rna(b0), b1h = tf32_rna(b1);
    uint32_t b0l = tf32_rna(b0 - __uint_as_float(b0h));
    uint32_t b1l = tf32_rna(b1 - __uint_as_float(b1h));
    g_Bf[idx] = make_float4(__uint_as_float(b0h), __uint_as_float(b1h),
                            __uint_as_float(b0l), __uint_as_float(b1l));
}

// ---------- main ----------
__global__ void __launch_bounds__(NTHR, 4)
econv_kernel(const float* __restrict__ x,
             const float* __restrict__ bias,
             float* __restrict__ out)
{
    extern __shared__ float smem[];
    float2* xs[2];
    xs[0] = (float2*)smem;
    xs[1] = xs[0] + XS_ELEMS;
    float* Ys = smem + 4 * XS_ELEMS;            // [k][vox], stride YS_STRIDE

    const int tid  = threadIdx.x;
    const int wid  = tid >> 5;                  // 0..3
    const int lid  = tid & 31;
    const int gid  = lid >> 2;                  // 0..7
    const int tidg = lid & 3;                   // 0..3
    const int b    = blockIdx.y;
    const int t    = blockIdx.x;                // 6x6x24
    const int tz   = t / 36;
    const int ty   = (t % 36) / 6;
    const int tx   = t % 6;
    const int z0   = tz * TZ, y0 = ty * TY, x0 = tx * TX;

    const size_t x_chan = (size_t)DIMS * DIMS * DIMS;
    const float* xb = x + (size_t)b * NI * x_chan;

    // zero the K-pad rows (20..23) once
    #pragma unroll
    for (int k = 0; k < 5; k++) {
        int idx = tid + k * NTHR;
        if (idx < 4 * YS_STRIDE) Ys[20 * YS_STRIDE + idx] = 0.0f;
    }

    // accumulators: [mt][nt][4]  (32 vox x 64 out per warp)
    float acc[64];
    #pragma unroll
    for (int k = 0; k < 64; k++) acc[k] = 0.0f;

    // ---- halo prefetch for a channel pair ----
    float pre0[7], pre1[7];
    auto pf_x = [&](int pair) {
        const float* c0 = xb + (size_t)(2 * pair) * x_chan;
        const float* c1 = c0 + x_chan;
        #pragma unroll
        for (int k = 0; k < 7; k++) {
            int idx = tid + k * NTHR;
            float v0 = 0.0f, v1 = 0.0f;
            if (idx < XS_ELEMS) {
                int zz = idx / (HX * HY);
                int rr = idx % (HX * HY);
                int yy = rr / HX, xx = rr % HX;
                int gz = z0 + zz - 2, gy = y0 + yy - 2, gx = x0 + xx - 2;
                if ((unsigned)gz < (unsigned)DIMS &&
                    (unsigned)gy < (unsigned)DIMS &&
                    (unsigned)gx < (unsigned)DIMS) {
                    int off = (gz * DIMS + gy) * DIMS + gx;
                    v0 = __ldg(&c0[off]);
                    v1 = __ldg(&c1[off]);
                }
            }
            pre0[k] = v0; pre1[k] = v1;
        }
    };
    auto cm_x = [&](float2* dst) {
        #pragma unroll
        for (int k = 0; k < 7; k++) {
            int idx = tid + k * NTHR;
            if (idx < XS_ELEMS) dst[idx] = make_float2(pre0[k], pre1[k]);
        }
    };

    // ---- radial sums for 2 channels at once (packed f32x2 adds) ----
    auto radial = [&](const float2* xsrc) {
        const int vz = tid >> 6, vy = (tid >> 3) & 7, vx = tid & 7;
        const unsigned long long* xu = (const unsigned long long*)xsrc;
        unsigned long long yr[NP];
        #pragma unroll
        for (int p = 0; p < NP; p++) yr[p] = 0ULL;
        #pragma unroll
        for (int dz = 0; dz < 5; dz++) {
            #pragma unroll
            for (int dy = 0; dy < 5; dy++) {
                const unsigned long long* row =
                    &xu[((vz + dz) * HY + (vy + dy)) * HX + vx];
                #pragma unroll
                for (int dx = 0; dx < 5; dx++) {
                    const int p = p_of_r2((dz - 2) * (dz - 2) +
                                          (dy - 2) * (dy - 2) +
                                          (dx - 2) * (dx - 2));
                    asm("add.rn.f32x2 %0, %0, %1;" : "+l"(yr[p]) : "l"(row[dx]));
                }
            }
        }
        #pragma unroll
        for (int p = 0; p < NP; p++) {
            float2 v = *(float2*)&yr[p];
            Ys[p * YS_STRIDE + tid]        = v.x;   // ch0 -> k rows 0..9
            Ys[(p + 10) * YS_STRIDE + tid] = v.y;   // ch1 -> k rows 10..19
        }
    };

    // ---- GEMM: 3xTF32 mma over this pair's K=24 (rows 20..23 zero) ----
    auto gemm = [&](int pair) {
        const float4* bsrc = g_Bf + pair * (3 * 8 * 32);
        #pragma unroll
        for (int ks = 0; ks < 3; ks++) {
            float4 bf[8];
            #pragma unroll
            for (int nt = 0; nt < 8; nt++)
                bf[nt] = __ldg(&bsrc[(ks * 8 + nt) * 32 + lid]);
            uint32_t Ah[2][4], Al[2][4];
            #pragma unroll
            for (int mt = 0; mt < 2; mt++) {
                const int vb = wid * 32 + mt * 16 + gid;
                const float* yk = Ys + (ks * 8 + tidg) * YS_STRIDE;
                float a[4];
                a[0] = yk[vb];
                a[1] = yk[vb + 8];
                a[2] = yk[4 * YS_STRIDE + vb];
                a[3] = yk[4 * YS_STRIDE + vb + 8];
                #pragma unroll
                for (int r = 0; r < 4; r++) {
                    Ah[mt][r] = tf32_rna(a[r]);
                    Al[mt][r] = tf32_rna(a[r] - __uint_as_float(Ah[mt][r]));
                }
            }
            #pragma unroll
            for (int nt = 0; nt < 8; nt++) {
                uint32_t b0h = __float_as_uint(bf[nt].x);
                uint32_t b1h = __float_as_uint(bf[nt].y);
                uint32_t b0l = __float_as_uint(bf[nt].z);
                uint32_t b1l = __float_as_uint(bf[nt].w);
                #pragma unroll
                for (int mt = 0; mt < 2; mt++) {
                    float* c = &acc[(mt * 8 + nt) * 4];
                    mma_tf32(c, Ah[mt][0], Ah[mt][1], Ah[mt][2], Ah[mt][3], b0h, b1h);
                    mma_tf32(c, Al[mt][0], Al[mt][1], Al[mt][2], Al[mt][3], b0h, b1h);
                    mma_tf32(c, Ah[mt][0], Ah[mt][1], Ah[mt][2], Ah[mt][3], b0l, b1l);
                }
            }
        }
    };

    // ---- pipeline prologue ----
    pf_x(0);
    cm_x(xs[0]);
    __syncthreads();
    radial(xs[0]);

    // ---- main loop over 16 channel pairs ----
    #pragma unroll 1
    for (int pair = 0; pair < NPAIR; pair++) {
        if (pair + 1 < NPAIR) pf_x(pair + 1);    // LDGs in flight behind gemm
        __syncthreads();                         // Ys(pair) visible
        gemm(pair);
        if (pair + 1 < NPAIR) {
            cm_x(xs[(pair + 1) & 1]);
            __syncthreads();                     // gemm done with Ys; new xs ok
            radial(xs[(pair + 1) & 1]);          // build Ys(pair+1)
        }
    }

    // ---- epilogue: stage through smem (aliases Ys) for coalesced stores ----
    __syncthreads();
    float* stage = Ys;                           // [c16][vox], stride YS_STRIDE
    #pragma unroll 1
    for (int chunk = 0; chunk < 4; chunk++) {
        if (chunk) __syncthreads();
        #pragma unroll
        for (int mt = 0; mt < 2; mt++) {
            #pragma unroll
            for (int nt2 = 0; nt2 < 2; nt2++) {
                const int nt = chunk * 2 + nt2;
                #pragma unroll
                for (int r = 0; r < 4; r++) {
                    int vox = wid * 32 + mt * 16 + gid + ((r >> 1) << 3);
                    int c16 = nt2 * 8 + 2 * tidg + (r & 1);
                    stage[c16 * YS_STRIDE + vox] = acc[(mt * 8 + nt) * 4 + r];
                }
            }
        }
        __syncthreads();
        // store 16 outputs x 128 vox: warp covers o16 = j*4 + wid
        #pragma unroll
        for (int j = 0; j < 4; j++) {
            const int o16  = j * 4 + wid;
            const int row  = lid >> 1;           // vox/8 (vz*8+vy)
            const int half = lid & 1;
            const int o    = chunk * 16 + o16;
            const float bb = __ldg(&bias[o]);
            float4 v = *(float4*)&stage[o16 * YS_STRIDE + row * 8 + half * 4];
            v.x += bb; v.y += bb; v.z += bb; v.w += bb;
            const int gz = z0 + (row >> 3), gy = y0 + (row & 7);
            float* dst = out + ((size_t)b * NO + o) * x_chan
                             + ((size_t)gz * DIMS + gy) * DIMS + x0 + half * 4;
            *(float4*)dst = v;
        }
    }
}

extern "C" void kernel_launch(void* const* d_in, const int* in_sizes, int n_in,
                              void* d_out, int out_size)
{
    const float* x    = (const float*)d_in[0];   // [2,32,1,48,48,48]
    const float* w    = (const float*)d_in[1];   // [64,32,1,1,1,10]
    const float* bias = (const float*)d_in[2];   // [64]
    float* out = (float*)d_out;                  // [2,64,1,48,48,48]

    bprep_kernel<<<(NPAIR * 3 * 8 * 32 + 255) / 256, 256>>>(w);

    dim3 grid(864, 2);   // 6x6x24 spatial tiles x batch
    econv_kernel<<<grid, NTHR, SMEM_BYTES>>>(x, bias, out);
}

// round 8
// speedup vs baseline: 1.3430x; 1.2536x over previous
#include <cuda_runtime.h>
#include <cstdint>

// EquiLocalPatOrientConvolution: B=2, I=32, O=64, D=H=W=48, K=5 (pad 2).
// v8 = v7 + bank-conflict-free xs layout (row stride 24 float2 so the two
// vy rows in each 16-lane LDS.64 phase hit disjoint bank halves).
// radial f32x2 (2 ch/pass) -> Ys[k][vox] -> mma.sync m16n8k8 tf32 3x-split.

#define DIMS  48
#define TX    8
#define TY    8
#define TZ    2
#define HX    12
#define HY    12
#define HZ    6
#define XSTR  24                        // padded row stride (float2)
#define NI    32
#define NO    64
#define NP    10
#define Y0C   0.28209479177387814f
#define NTHR  128
#define NVOX  128
#define NPAIR 16

#define XS_ELEMS   (HZ * HY * XSTR)     // 1728 float2 per buffer (padded)
#define YS_STRIDE  136                  // 128 vox + 8 pad
#define YS_ROWS    24                   // k = 0..19 data, 20..23 zero
#define YS_FLOATS  (YS_ROWS * YS_STRIDE)
#define SMEM_FLOATS (2 * 2 * XS_ELEMS + YS_FLOATS)
#define SMEM_BYTES  (SMEM_FLOATS * 4 + 256)

__device__ __host__ constexpr int p_of_r2(int r2) {
    return r2 <= 6 ? r2 : (r2 == 8 ? 7 : (r2 == 9 ? 8 : 9));
}

// B fragments: [pair][ks][nt][lane] -> float4 {b0hi, b1hi, b0lo, b1lo}
__device__ float4 g_Bf[NPAIR * 3 * 8 * 32];

__device__ __forceinline__ uint32_t tf32_rna(float x) {
    uint32_t r;
    asm("cvt.rna.tf32.f32 %0, %1;" : "=r"(r) : "f"(x));
    return r;
}

__device__ __forceinline__ void mma_tf32(float* c,
                                         uint32_t a0, uint32_t a1, uint32_t a2, uint32_t a3,
                                         uint32_t b0, uint32_t b1) {
    asm("mma.sync.aligned.m16n8k8.row.col.f32.tf32.tf32.f32 "
        "{%0,%1,%2,%3}, {%4,%5,%6,%7}, {%8,%9}, {%0,%1,%2,%3};"
        : "+f"(c[0]), "+f"(c[1]), "+f"(c[2]), "+f"(c[3])
        : "r"(a0), "r"(a1), "r"(a2), "r"(a3), "r"(b0), "r"(b1));
}

// ---------- prep: W[o][ci][p] -> B-fragment layout, Y0 folded, hi/lo tf32 ----------
__global__ void bprep_kernel(const float* __restrict__ wg) {
    int idx = blockIdx.x * 256 + threadIdx.x;
    if (idx >= NPAIR * 3 * 8 * 32) return;
    int lane = idx & 31;
    int r    = idx >> 5;
    int nt   = r & 7;  r >>= 3;
    int ks   = r % 3;
    int pair = r / 3;
    int gid = lane >> 2, tidg = lane & 3;
    int o = nt * 8 + gid;
    auto getw = [&](int k) -> float {
        if (k >= 20) return 0.0f;
        int ci = pair * 2 + k / 10;
        int p  = k % 10;
        return Y0C * wg[o * (NI * NP) + ci * NP + p];
    };
    float b0 = getw(ks * 8 + tidg);
    float b1 = getw(ks * 8 + tidg + 4);
    uint32_t b0h = tf32_rna(b0), b1h = tf32_rna(b1);
    uint32_t b0l = tf32_rna(b0 - __uint_as_float(b0h));
    uint32_t b1l = tf32_rna(b1 - __uint_as_float(b1h));
    g_Bf[idx] = make_float4(__uint_as_float(b0h), __uint_as_float(b1h),
                            __uint_as_float(b0l), __uint_as_float(b1l));
}

// ---------- main ----------
__global__ void __launch_bounds__(NTHR, 4)
econv_kernel(const float* __restrict__ x,
             const float* __restrict__ bias,
             float* __restrict__ out)
{
    extern __shared__ float smem[];
    float2* xs[2];
    xs[0] = (float2*)smem;
    xs[1] = xs[0] + XS_ELEMS;
    float* Ys = smem + 4 * XS_ELEMS;            // [k][vox], stride YS_STRIDE

    const int tid  = threadIdx.x;
    const int wid  = tid >> 5;                  // 0..3
    const int lid  = tid & 31;
    const int gid  = lid >> 2;                  // 0..7
    const int tidg = lid & 3;                   // 0..3
    const int b    = blockIdx.y;
    const int t    = blockIdx.x;                // 6x6x24
    const int tz   = t / 36;
    const int ty   = (t % 36) / 6;
    const int tx   = t % 6;
    const int z0   = tz * TZ, y0 = ty * TY, x0 = tx * TX;

    const size_t x_chan = (size_t)DIMS * DIMS * DIMS;
    const float* xb = x + (size_t)b * NI * x_chan;

    // zero the K-pad rows (20..23) once
    #pragma unroll
    for (int k = 0; k < 5; k++) {
        int idx = tid + k * NTHR;
        if (idx < 4 * YS_STRIDE) Ys[20 * YS_STRIDE + idx] = 0.0f;
    }

    // accumulators: [mt][nt][4]  (32 vox x 64 out per warp)
    float acc[64];
    #pragma unroll
    for (int k = 0; k < 64; k++) acc[k] = 0.0f;

    // ---- halo prefetch for a channel pair (864 real cells of 12x12x6) ----
    float pre0[7], pre1[7];
    auto pf_x = [&](int pair) {
        const float* c0 = xb + (size_t)(2 * pair) * x_chan;
        const float* c1 = c0 + x_chan;
        #pragma unroll
        for (int k = 0; k < 7; k++) {
            int idx = tid + k * NTHR;            // 0..864 over (zz,yy,xx)
            float v0 = 0.0f, v1 = 0.0f;
            if (idx < HZ * HY * HX) {
                int zz = idx / (HX * HY);
                int rr = idx % (HX * HY);
                int yy = rr / HX, xx = rr % HX;
                int gz = z0 + zz - 2, gy = y0 + yy - 2, gx = x0 + xx - 2;
                if ((unsigned)gz < (unsigned)DIMS &&
                    (unsigned)gy < (unsigned)DIMS &&
                    (unsigned)gx < (unsigned)DIMS) {
                    int off = (gz * DIMS + gy) * DIMS + gx;
                    v0 = __ldg(&c0[off]);
                    v1 = __ldg(&c1[off]);
                }
            }
            pre0[k] = v0; pre1[k] = v1;
        }
    };
    auto cm_x = [&](float2* dst) {
        #pragma unroll
        for (int k = 0; k < 7; k++) {
            int idx = tid + k * NTHR;
            if (idx < HZ * HY * HX) {
                int zz = idx / (HX * HY);
                int rr = idx % (HX * HY);
                int yy = rr / HX, xx = rr % HX;
                dst[(zz * HY + yy) * XSTR + xx] = make_float2(pre0[k], pre1[k]);
            }
        }
    };

    // ---- radial sums for 2 channels at once (packed f32x2 adds) ----
    auto radial = [&](const float2* xsrc) {
        const int vz = tid >> 6, vy = (tid >> 3) & 7, vx = tid & 7;
        const unsigned long long* xu = (const unsigned long long*)xsrc;
        unsigned long long yr[NP];
        #pragma unroll
        for (int p = 0; p < NP; p++) yr[p] = 0ULL;
        #pragma unroll
        for (int dz = 0; dz < 5; dz++) {
            #pragma unroll
            for (int dy = 0; dy < 5; dy++) {
                const unsigned long long* row =
                    &xu[((vz + dz) * HY + (vy + dy)) * XSTR + vx];
                #pragma unroll
                for (int dx = 0; dx < 5; dx++) {
                    const int p = p_of_r2((dz - 2) * (dz - 2) +
                                          (dy - 2) * (dy - 2) +
                                          (dx - 2) * (dx - 2));
                    asm("add.rn.f32x2 %0, %0, %1;" : "+l"(yr[p]) : "l"(row[dx]));
                }
            }
        }
        #pragma unroll
        for (int p = 0; p < NP; p++) {
            float2 v = *(float2*)&yr[p];
            Ys[p * YS_STRIDE + tid]        = v.x;   // ch0 -> k rows 0..9
            Ys[(p + 10) * YS_STRIDE + tid] = v.y;   // ch1 -> k rows 10..19
        }
    };

    // ---- GEMM: 3xTF32 mma over this pair's K=24 (rows 20..23 zero) ----
    auto gemm = [&](int pair) {
        const float4* bsrc = g_Bf + pair * (3 * 8 * 32);
        #pragma unroll
        for (int ks = 0; ks < 3; ks++) {
            float4 bf[8];
            #pragma unroll
            for (int nt = 0; nt < 8; nt++)
                bf[nt] = __ldg(&bsrc[(ks * 8 + nt) * 32 + lid]);
            uint32_t Ah[2][4], Al[2][4];
            #pragma unroll
            for (int mt = 0; mt < 2; mt++) {
                const int vb = wid * 32 + mt * 16 + gid;
                const float* yk = Ys + (ks * 8 + tidg) * YS_STRIDE;
                float a[4];
                a[0] = yk[vb];
                a[1] = yk[vb + 8];
                a[2] = yk[4 * YS_STRIDE + vb];
                a[3] = yk[4 * YS_STRIDE + vb + 8];
                #pragma unroll
                for (int r = 0; r < 4; r++) {
                    Ah[mt][r] = tf32_rna(a[r]);
                    Al[mt][r] = tf32_rna(a[r] - __uint_as_float(Ah[mt][r]));
                }
            }
            #pragma unroll
            for (int nt = 0; nt < 8; nt++) {
                uint32_t b0h = __float_as_uint(bf[nt].x);
                uint32_t b1h = __float_as_uint(bf[nt].y);
                uint32_t b0l = __float_as_uint(bf[nt].z);
                uint32_t b1l = __float_as_uint(bf[nt].w);
                #pragma unroll
                for (int mt = 0; mt < 2; mt++) {
                    float* c = &acc[(mt * 8 + nt) * 4];
                    mma_tf32(c, Ah[mt][0], Ah[mt][1], Ah[mt][2], Ah[mt][3], b0h, b1h);
                    mma_tf32(c, Al[mt][0], Al[mt][1], Al[mt][2], Al[mt][3], b0h, b1h);
                    mma_tf32(c, Ah[mt][0], Ah[mt][1], Ah[mt][2], Ah[mt][3], b0l, b1l);
                }
            }
        }
    };

    // ---- pipeline prologue ----
    pf_x(0);
    cm_x(xs[0]);
    __syncthreads();
    radial(xs[0]);

    // ---- main loop over 16 channel pairs ----
    #pragma unroll 1
    for (int pair = 0; pair < NPAIR; pair++) {
        if (pair + 1 < NPAIR) pf_x(pair + 1);    // LDGs in flight behind gemm
        __syncthreads();                         // Ys(pair) visible
        gemm(pair);
        if (pair + 1 < NPAIR) {
            cm_x(xs[(pair + 1) & 1]);
            __syncthreads();                     // gemm done with Ys; new xs ok
            radial(xs[(pair + 1) & 1]);          // build Ys(pair+1)
        }
    }

    // ---- epilogue: stage through smem (aliases Ys) for coalesced stores ----
    __syncthreads();
    float* stage = Ys;                           // [c16][vox], stride YS_STRIDE
    #pragma unroll 1
    for (int chunk = 0; chunk < 4; chunk++) {
        if (chunk) __syncthreads();
        #pragma unroll
        for (int mt = 0; mt < 2; mt++) {
            #pragma unroll
            for (int nt2 = 0; nt2 < 2; nt2++) {
                const int nt = chunk * 2 + nt2;
                #pragma unroll
                for (int r = 0; r < 4; r++) {
                    int vox = wid * 32 + mt * 16 + gid + ((r >> 1) << 3);
                    int c16 = nt2 * 8 + 2 * tidg + (r & 1);
                    stage[c16 * YS_STRIDE + vox] = acc[(mt * 8 + nt) * 4 + r];
                }
            }
        }
        __syncthreads();
        #pragma unroll
        for (int j = 0; j < 4; j++) {
            const int o16  = j * 4 + wid;
            const int row  = lid >> 1;           // vox/8 (vz*8+vy)
            const int half = lid & 1;
            const int o    = chunk * 16 + o16;
            const float bb = __ldg(&bias[o]);
            float4 v = *(float4*)&stage[o16 * YS_STRIDE + row * 8 + half * 4];
            v.x += bb; v.y += bb; v.z += bb; v.w += bb;
            const int gz = z0 + (row >> 3), gy = y0 + (row & 7);
            float* dst = out + ((size_t)b * NO + o) * x_chan
                             + ((size_t)gz * DIMS + gy) * DIMS + x0 + half * 4;
            *(float4*)dst = v;
        }
    }
}

extern "C" void kernel_launch(void* const* d_in, const int* in_sizes, int n_in,
                              void* d_out, int out_size)
{
    const float* x    = (const float*)d_in[0];   // [2,32,1,48,48,48]
    const float* w    = (const float*)d_in[1];   // [64,32,1,1,1,10]
    const float* bias = (const float*)d_in[2];   // [64]
    float* out = (float*)d_out;                  // [2,64,1,48,48,48]

    bprep_kernel<<<(NPAIR * 3 * 8 * 32 + 255) / 256, 256>>>(w);

    dim3 grid(864, 2);   // 6x6x24 spatial tiles x batch
    econv_kernel<<<grid, NTHR, SMEM_BYTES>>>(x, bias, out);
}